// round 6
// baseline (speedup 1.0000x reference)
#include <cuda_runtime.h>
#include <cuda_fp16.h>
#include <cstdint>
#include <math.h>

#define H     1024
#define IDIM  2048
#define E     8
#define NTOK  8192
#define MAXROWS 8192
#define BKP   40   // padded K-stride in halves (80B rows: 16B-aligned, conflict-free ldmatrix)

// ---------------- scratch (static device memory; no allocations) ----------------
__device__ int    g_count[E];
__device__ int    g_dest[E * MAXROWS];     // n*2 + slot
__device__ float  g_gw[E * MAXROWS];       // gate weight (softmax prob)
__device__ __half g_xh [ (size_t)NTOK * H ];          // x in fp16
__device__ __half g_w1h[ (size_t)E * IDIM * H ];      // W1 in fp16
__device__ __half g_w2h[ (size_t)E * H * IDIM ];      // W2 in fp16
__device__ __half g_hid[ (size_t)E * MAXROWS * IDIM ];// fc1 outputs (silu), per (e,pos)
__device__ float  g_contrib[ (size_t)2 * NTOK * H ];  // per (slot, token) fc2 output

// ---------------- small kernels ----------------
__global__ void zero_counts_kernel() {
    if (threadIdx.x < E) g_count[threadIdx.x] = 0;
}

__global__ void gate_kernel(const float* __restrict__ x, const float* __restrict__ Wg) {
    __shared__ float sWg[E][H];
    int tid = threadIdx.x;
    for (int i = tid; i < E * H; i += blockDim.x) sWg[i / H][i % H] = Wg[i];
    __syncthreads();
    int warp = tid >> 5, lane = tid & 31;
    int n = blockIdx.x * 8 + warp;
    const float* xr = x + (size_t)n * H;
    float acc[E];
#pragma unroll
    for (int e = 0; e < E; e++) acc[e] = 0.f;
    for (int j = lane; j < H; j += 32) {
        float xv = xr[j];
#pragma unroll
        for (int e = 0; e < E; e++) acc[e] += xv * sWg[e][j];
    }
#pragma unroll
    for (int e = 0; e < E; e++) {
#pragma unroll
        for (int o = 16; o > 0; o >>= 1) acc[e] += __shfl_xor_sync(0xffffffffu, acc[e], o);
    }
    if (lane == 0) {
        float m = acc[0];
#pragma unroll
        for (int e = 1; e < E; e++) m = fmaxf(m, acc[e]);
        float p[E], s = 0.f;
#pragma unroll
        for (int e = 0; e < E; e++) { p[e] = expf(acc[e] - m); s += p[e]; }
        float inv = 1.f / s;
#pragma unroll
        for (int e = 0; e < E; e++) p[e] *= inv;
        int i1 = 0;
#pragma unroll
        for (int e = 1; e < E; e++) if (p[e] > p[i1]) i1 = e;   // ties -> lowest idx
        int i2 = (i1 == 0) ? 1 : 0;
#pragma unroll
        for (int e = 0; e < E; e++) if (e != i1 && p[e] > p[i2]) i2 = e;
        int pos1 = atomicAdd(&g_count[i1], 1);
        g_dest[i1 * MAXROWS + pos1] = n * 2;
        g_gw  [i1 * MAXROWS + pos1] = p[i1];
        int pos2 = atomicAdd(&g_count[i2], 1);
        g_dest[i2 * MAXROWS + pos2] = n * 2 + 1;
        g_gw  [i2 * MAXROWS + pos2] = p[i2];
    }
}

#define NX4  ((size_t)NTOK * H / 4)
#define NW14 ((size_t)E * IDIM * H / 4)
__global__ void convert_kernel(const float4* __restrict__ x,
                               const float4* __restrict__ W1,
                               const float4* __restrict__ W2) {
    size_t i = (size_t)blockIdx.x * blockDim.x + threadIdx.x;
    const float4* s; __half* d; size_t off;
    if (i < NX4)             { s = x;  d = g_xh;  off = i; }
    else if (i < NX4 + NW14) { s = W1; d = g_w1h; off = i - NX4; }
    else                     { s = W2; d = g_w2h; off = i - NX4 - NW14; }
    float4 v = s[off];
    __half2 h0 = __floats2half2_rn(v.x, v.y);
    __half2 h1 = __floats2half2_rn(v.z, v.w);
    uint2 pack;
    pack.x = *reinterpret_cast<uint32_t*>(&h0);
    pack.y = *reinterpret_cast<uint32_t*>(&h1);
    *reinterpret_cast<uint2*>(d + off * 4) = pack;
}

// ---------------- MMA helpers ----------------
__device__ __forceinline__ void ldm_x4(uint32_t& r0, uint32_t& r1, uint32_t& r2, uint32_t& r3, uint32_t addr) {
    asm volatile("ldmatrix.sync.aligned.m8n8.x4.shared.b16 {%0,%1,%2,%3}, [%4];"
                 : "=r"(r0), "=r"(r1), "=r"(r2), "=r"(r3) : "r"(addr));
}
__device__ __forceinline__ void mma_16816(float* c, const uint32_t* a, const uint32_t* b) {
    asm volatile("mma.sync.aligned.m16n8k16.row.col.f32.f16.f16.f32 "
                 "{%0,%1,%2,%3},{%4,%5,%6,%7},{%8,%9},{%0,%1,%2,%3};"
                 : "+f"(c[0]), "+f"(c[1]), "+f"(c[2]), "+f"(c[3])
                 : "r"(a[0]), "r"(a[1]), "r"(a[2]), "r"(a[3]), "r"(b[0]), "r"(b[1]));
}

// ---------------- grouped GEMM (BM=128, BN=128, BK=32, 256 thr / 8 warps) ----------------
template <bool FC1>
__global__ void __launch_bounds__(256) moe_gemm_kernel() {
    constexpr int K = FC1 ? H : IDIM;
    const int e  = blockIdx.z;
    const int Ne = g_count[e];
    const int m0 = blockIdx.x * 128;
    if (m0 >= Ne) return;
    const int n0 = blockIdx.y * 128;

    __shared__ __half sA[128][BKP];
    __shared__ __half sB[128][BKP];
    __shared__ int    sRow[128];

    const int tid  = threadIdx.x;
    const int lane = tid & 31, warp = tid >> 5;
    const int wm = (warp >> 2) * 64;   // 2 warps along M
    const int wn = (warp & 3) * 32;    // 4 warps along N

    if (tid < 128) {
        int rg = m0 + tid;
        int ro = -1;
        if (rg < Ne) {
            if (FC1) ro = (g_dest[e * MAXROWS + rg] >> 1) * H;       // token row in g_xh
            else     ro = (e * MAXROWS + rg) * IDIM;                 // hid row
        }
        sRow[tid] = ro;
    }
    __syncthreads();

    const __half* Abase = FC1 ? g_xh : g_hid;
    const __half* Bbase = FC1 ? (g_w1h + (size_t)e * IDIM * H)
                              : (g_w2h + (size_t)e * H * IDIM);

    float acc[4][4][4];
#pragma unroll
    for (int i = 0; i < 4; i++)
#pragma unroll
        for (int j = 0; j < 4; j++)
#pragma unroll
            for (int q = 0; q < 4; q++) acc[i][j][q] = 0.f;

    const int r_ld = tid >> 2;          // 0..63 (+64 for second half)
    const int c_ld = (tid & 3) << 3;    // 0,8,16,24

    uint4 ra[2], rb[2];
#pragma unroll
    for (int u = 0; u < 2; u++) {
        int r = r_ld + u * 64;
        int ro = sRow[r];
        ra[u] = (ro >= 0) ? *reinterpret_cast<const uint4*>(Abase + (size_t)ro + c_ld)
                          : make_uint4(0u, 0u, 0u, 0u);
        rb[u] = *reinterpret_cast<const uint4*>(Bbase + (size_t)(n0 + r) * K + c_ld);
    }

    for (int k0 = 0; k0 < K; k0 += 32) {
        __syncthreads();
#pragma unroll
        for (int u = 0; u < 2; u++) {
            int r = r_ld + u * 64;
            *reinterpret_cast<uint4*>(&sA[r][c_ld]) = ra[u];
            *reinterpret_cast<uint4*>(&sB[r][c_ld]) = rb[u];
        }
        __syncthreads();
        if (k0 + 32 < K) {
            int k1 = k0 + 32;
#pragma unroll
            for (int u = 0; u < 2; u++) {
                int r = r_ld + u * 64;
                int ro = sRow[r];
                ra[u] = (ro >= 0) ? *reinterpret_cast<const uint4*>(Abase + (size_t)ro + k1 + c_ld)
                                  : make_uint4(0u, 0u, 0u, 0u);
                rb[u] = *reinterpret_cast<const uint4*>(Bbase + (size_t)(n0 + r) * K + k1 + c_ld);
            }
        }
#pragma unroll
        for (int ks = 0; ks < 2; ks++) {
            const int kk = ks * 16;
            uint32_t a[4][4], b[4][2];
#pragma unroll
            for (int im = 0; im < 4; im++) {
                int r = wm + im * 16 + (lane & 15);
                int c = kk + ((lane >> 4) << 3);
                uint32_t addr = (uint32_t)__cvta_generic_to_shared(&sA[r][c]);
                ldm_x4(a[im][0], a[im][1], a[im][2], a[im][3], addr);
            }
#pragma unroll
            for (int jp = 0; jp < 2; jp++) {
                int r = wn + jp * 16 + (lane & 7) + ((lane & 16) >> 1);
                int c = kk + (lane & 8);
                uint32_t addr = (uint32_t)__cvta_generic_to_shared(&sB[r][c]);
                ldm_x4(b[2 * jp][0], b[2 * jp][1], b[2 * jp + 1][0], b[2 * jp + 1][1], addr);
            }
#pragma unroll
            for (int im = 0; im < 4; im++)
#pragma unroll
                for (int jn = 0; jn < 4; jn++)
                    mma_16816(acc[im][jn], a[im], b[jn]);
        }
    }

    // epilogue
    const int lr = lane >> 2;
    const int lc = (lane & 3) << 1;
#pragma unroll
    for (int im = 0; im < 4; im++) {
#pragma unroll
        for (int hh = 0; hh < 2; hh++) {
            int rl = wm + im * 16 + lr + hh * 8;
            int rg = m0 + rl;
            if (rg < Ne) {
                if (FC1) {
                    size_t base = ((size_t)e * MAXROWS + rg) * IDIM;
#pragma unroll
                    for (int jn = 0; jn < 4; jn++) {
                        int col = n0 + wn + jn * 8 + lc;
                        float v0 = acc[im][jn][hh * 2 + 0];
                        float v1 = acc[im][jn][hh * 2 + 1];
                        v0 = v0 / (1.f + expf(-v0));
                        v1 = v1 / (1.f + expf(-v1));
                        *reinterpret_cast<__half2*>(&g_hid[base + col]) = __floats2half2_rn(v0, v1);
                    }
                } else {
                    float w = g_gw[e * MAXROWS + rg];
                    int   d = g_dest[e * MAXROWS + rg];
                    size_t base = (size_t)(d & 1) * NTOK * H + (size_t)(d >> 1) * H;
#pragma unroll
                    for (int jn = 0; jn < 4; jn++) {
                        int col = n0 + wn + jn * 8 + lc;
                        float2 v = make_float2(w * acc[im][jn][hh * 2 + 0],
                                               w * acc[im][jn][hh * 2 + 1]);
                        *reinterpret_cast<float2*>(&g_contrib[base + col]) = v;
                    }
                }
            }
        }
    }
}

__global__ void combine_kernel(float* __restrict__ out) {
    size_t i = (size_t)blockIdx.x * blockDim.x + threadIdx.x;
    float4 a = *reinterpret_cast<const float4*>(g_contrib + 4 * i);
    float4 b = *reinterpret_cast<const float4*>(g_contrib + (size_t)NTOK * H + 4 * i);
    float4 o;
    o.x = a.x + b.x; o.y = a.y + b.y; o.z = a.z + b.z; o.w = a.w + b.w;
    reinterpret_cast<float4*>(out)[i] = o;
}

// ---------------- launch ----------------
extern "C" void kernel_launch(void* const* d_in, const int* in_sizes, int n_in,
                              void* d_out, int out_size) {
    const float* x  = (const float*)d_in[0];
    const float* Wg = (const float*)d_in[1];
    const float* W1 = (const float*)d_in[2];
    const float* W2 = (const float*)d_in[3];
    float* out = (float*)d_out;

    zero_counts_kernel<<<1, 32>>>();
    gate_kernel<<<NTOK / 8, 256>>>(x, Wg);
    size_t total4 = NX4 + 2 * NW14;            // 10,485,760 float4s
    convert_kernel<<<(unsigned)(total4 / 256), 256>>>(
        (const float4*)x, (const float4*)W1, (const float4*)W2);
    moe_gemm_kernel<true ><<<dim3(MAXROWS / 128, IDIM / 128, E), 256>>>();
    moe_gemm_kernel<false><<<dim3(MAXROWS / 128, H    / 128, E), 256>>>();
    combine_kernel<<<(NTOK * H) / 1024, 256>>>(out);
}